// round 11
// baseline (speedup 1.0000x reference)
#include <cuda_runtime.h>

#define FRAME 2048
#define IDX(i) ((i) ^ (((i) >> 4) & 15))   // float2 FFT-buffer swizzle

// ---- device-global lag table ----
__device__ float4 g_lagpack[2048];    // (lag, floor_bits, ceil_bits, 0)

__global__ void setup_kernel(int M) {
    int m = blockIdx.x * blockDim.x + threadIdx.x;
    if (m >= M || m >= 2048) return;
    double midi64 = 5.0 + (double)m * 0.05;
    float  midi32 = (float)midi64;
    double e      = ((double)midi32 - 69.0) / 12.0;
    double lag64  = 22050.0 / (440.0 * exp2(e));
    float  lag32  = (float)lag64;
    int fi = (int)floorf(lag32), ci = (int)ceilf(lag32);
    g_lagpack[m] = make_float4(lag32, __int_as_float(fi), __int_as_float(ci), 0.f);
}

__device__ __forceinline__ float2 cmul(float2 a, float2 b) {
    return make_float2(fmaf(a.x, b.x, -a.y * b.y), fmaf(a.x, b.y, a.y * b.x));
}
__device__ __forceinline__ float2 cadd(float2 a, float2 b) { return make_float2(a.x + b.x, a.y + b.y); }
__device__ __forceinline__ float2 csub(float2 a, float2 b) { return make_float2(a.x - b.x, a.y - b.y); }

template<bool INV>
__device__ __forceinline__ void dft4(float2 a, float2 b, float2 c, float2 d, float2* o) {
    float2 p = cadd(a, c), m = csub(a, c);
    float2 q = cadd(b, d), n = csub(b, d);
    o[0] = cadd(p, q);
    o[2] = csub(p, q);
    if (!INV) { o[1] = make_float2(m.x + n.y, m.y - n.x); o[3] = make_float2(m.x - n.y, m.y + n.x); }
    else      { o[1] = make_float2(m.x - n.y, m.y + n.x); o[3] = make_float2(m.x + n.y, m.y - n.x); }
}

template<bool INV>
__device__ __forceinline__ void omega8(const float2* O, float2& o1, float2& o2, float2& o3) {
    const float s2 = 0.70710678118654752f;
    if (!INV) {
        o1 = make_float2(s2 * (O[1].x + O[1].y), s2 * (O[1].y - O[1].x));
        o2 = make_float2(O[2].y, -O[2].x);
        o3 = make_float2(s2 * (O[3].y - O[3].x), -s2 * (O[3].x + O[3].y));
    } else {
        o1 = make_float2(s2 * (O[1].x - O[1].y), s2 * (O[1].y + O[1].x));
        o2 = make_float2(-O[2].y, O[2].x);
        o3 = make_float2(-s2 * (O[3].x + O[3].y), s2 * (O[3].x - O[3].y));
    }
}

// compile-time store-offset constant: IDX(base + m*NS) == b2 ^ soff<NS>(m)
template<int NS>
__device__ __forceinline__ constexpr int soff(int m) {
    return NS == 1 ? m
         : NS == 8 ? ((m << 3) | ((m >> 1) & 3))
                   : ((m << 6) | ((m & 3) << 2));   // NS == 64
}
// per-thread store base (swizzle pre-applied), per NS
template<int NS>
__device__ __forceinline__ int sbase(int t) {
    if (NS == 1)  return (8 * t) ^ ((t >> 1) & 15);
    if (NS == 8)  return (((t >> 3) << 6) | (t & 7)) ^ (((t >> 3) & 3) << 2);
    /* NS == 64 */ return (((t >> 6) << 9) | (t & 63)) ^ ((t >> 4) & 3);
}

// ---- generic radix-8 Stockham stage (smem -> smem), computed twiddles ----
template<int NS, bool INV>
__device__ __forceinline__ void stage_r8(const float2* in, float2* out, int t, int tld) {
    float2 v[8];
#pragma unroll
    for (int k = 0; k < 8; k++) v[k] = in[tld + 256 * k];
    const int jm = t & (NS - 1);
    if (NS > 1) {
        float s, c;
        sincospif((float)jm * (1.0f / (4.0f * NS)), &s, &c);
        if (!INV) s = -s;
        float2 w1 = make_float2(c, s);
        v[1] = cmul(v[1], w1);
        float2 w2 = cmul(w1, w1);
        v[2] = cmul(v[2], w2);
        float2 w3 = cmul(w2, w1);
        v[3] = cmul(v[3], w3);
        float2 w4 = cmul(w2, w2);
        v[4] = cmul(v[4], w4);
        v[5] = cmul(v[5], cmul(w4, w1));
        v[6] = cmul(v[6], cmul(w4, w2));
        v[7] = cmul(v[7], cmul(w4, w3));
    }
    float2 E[4], O[4];
    dft4<INV>(v[0], v[2], v[4], v[6], E);
    dft4<INV>(v[1], v[3], v[5], v[7], O);
    float2 o1, o2, o3;
    omega8<INV>(O, o1, o2, o3);
    const int b2 = sbase<NS>(t);
    out[b2 ^ soff<NS>(0)] = cadd(E[0], O[0]);
    out[b2 ^ soff<NS>(4)] = csub(E[0], O[0]);
    out[b2 ^ soff<NS>(1)] = cadd(E[1], o1);
    out[b2 ^ soff<NS>(5)] = csub(E[1], o1);
    out[b2 ^ soff<NS>(2)] = cadd(E[2], o2);
    out[b2 ^ soff<NS>(6)] = csub(E[2], o2);
    out[b2 ^ soff<NS>(3)] = cadd(E[3], o3);
    out[b2 ^ soff<NS>(7)] = csub(E[3], o3);
    __syncthreads();
}

// ---- forward stage 1 (NS=1): reads 4 nonzero inputs from GLOBAL, v[4..7]=0 ----
// NOTE: does NOT end with a barrier — caller supplies the shared one.
__device__ __forceinline__ void stage1_fwd_zero(const float2* gx, float2* out, int t) {
    float2 v0 = gx[t], v1 = gx[t + 256], v2 = gx[t + 512], v3 = gx[t + 768];
    float2 E[4], O[4];
    E[0] = cadd(v0, v2);
    E[2] = csub(v0, v2);
    E[1] = make_float2(v0.x + v2.y, v0.y - v2.x);
    E[3] = make_float2(v0.x - v2.y, v0.y + v2.x);
    O[0] = cadd(v1, v3);
    O[2] = csub(v1, v3);
    O[1] = make_float2(v1.x + v3.y, v1.y - v3.x);
    O[3] = make_float2(v1.x - v3.y, v1.y + v3.x);
    float2 o1, o2, o3;
    omega8<false>(O, o1, o2, o3);
    const int b2 = sbase<1>(t);
    out[b2 ^ 0] = cadd(E[0], O[0]);
    out[b2 ^ 4] = csub(E[0], O[0]);
    out[b2 ^ 1] = cadd(E[1], o1);
    out[b2 ^ 5] = csub(E[1], o1);
    out[b2 ^ 2] = cadd(E[2], o2);
    out[b2 ^ 6] = csub(E[2], o2);
    out[b2 ^ 3] = cadd(E[3], o3);
    out[b2 ^ 7] = csub(E[3], o3);
}

// ---- final radix-4 stage (NS=512); STORE_ALL=false drops outputs >= 1024 ----
template<bool INV, bool STORE_ALL>
__device__ __forceinline__ void stage_r4_512(const float2* in, float2* out, int t, int tld) {
#pragma unroll
    for (int u = 0; u < 2; u++) {
        int j  = t + 256 * u;
        int jb = tld + 256 * u;
        float2 v0 = in[jb];
        float2 v1 = in[jb + 512];
        float2 v2 = in[jb + 1024];
        float2 v3 = in[jb + 1536];
        float s, c;
        sincospif((float)j * (1.0f / 1024.0f), &s, &c);
        if (!INV) s = -s;
        float2 w1 = make_float2(c, s);
        float2 w2 = cmul(w1, w1);
        float2 w3 = cmul(w2, w1);
        v1 = cmul(v1, w1); v2 = cmul(v2, w2); v3 = cmul(v3, w3);
        float2 a0 = cadd(v0, v2), a1 = csub(v0, v2);
        float2 a2 = cadd(v1, v3), a3 = csub(v1, v3);
        out[jb] = cadd(a0, a2);
        float2 y1 = (!INV) ? make_float2(a1.x + a3.y, a1.y - a3.x)
                           : make_float2(a1.x - a3.y, a1.y + a3.x);
        out[jb + 512] = y1;
        if (STORE_ALL) {
            out[jb + 1024] = csub(a0, a2);
            float2 y3 = (!INV) ? make_float2(a1.x - a3.y, a1.y + a3.x)
                               : make_float2(a1.x + a3.y, a1.y - a3.x);
            out[jb + 1536] = y3;
        }
    }
    __syncthreads();
}

// One CTA = one frame, 256 threads.
__global__ __launch_bounds__(256, 4) void yin_fft_kernel(
    const float* __restrict__ x, float* __restrict__ y, int M)
{
    __shared__ float2 bufA[2048];
    __shared__ float2 bufB[2048];
    __shared__ float4 ssq4[512];      // ssq[i] = s[i]   (prefix BEFORE element i)
    __shared__ float4 ssp4[512];      // ssp[i] = s[i+1] (prefix THROUGH element i)
    __shared__ float  warpAgg[8];

    const int t    = threadIdx.x;
    const int lane = t & 31;
    const int wid  = t >> 5;
    const int tld  = t ^ ((t >> 4) & 15);   // == IDX(t)
    const float* xf = x + (size_t)blockIdx.x * FRAME;

    // ---- FUSED: scan1 phase A + stage1 (G -> bufA), sharing ONE barrier ----
    float pr[8];
    float scanv;
    {
        float4 va = ((const float4*)xf)[2 * t];
        float4 vb = ((const float4*)xf)[2 * t + 1];
        float xr[8] = {va.x, va.y, va.z, va.w, vb.x, vb.y, vb.z, vb.w};
        float run = 0.f;
#pragma unroll
        for (int j = 0; j < 8; j++) { run += xr[j] * xr[j]; pr[j] = run; }
        float sc = run;
#pragma unroll
        for (int off = 1; off < 32; off <<= 1) {
            float o = __shfl_up_sync(0xffffffffu, sc, off);
            if (lane >= off) sc += o;
        }
        if (lane == 31) warpAgg[wid] = sc;
        scanv = sc - run;              // exclusive within-warp offset
    }
    stage1_fwd_zero((const float2*)xf, bufA, t);   // no internal barrier
    __syncthreads();                               // covers warpAgg AND bufA

    // ---- scan1 phase B: finish prefix sums, vectorized stores ----
    {
        float wOff = 0.f;
#pragma unroll
        for (int w = 0; w < 8; w++) if (w < wid) wOff += warpAgg[w];
        float tOff = wOff + scanv;
        float s0 = tOff + pr[0], s1 = tOff + pr[1], s2 = tOff + pr[2], s3 = tOff + pr[3];
        float s4 = tOff + pr[4], s5 = tOff + pr[5], s6 = tOff + pr[6], s7 = tOff + pr[7];
        ssq4[2 * t]     = make_float4(tOff, s0, s1, s2);
        ssq4[2 * t + 1] = make_float4(s3, s4, s5, s6);
        ssp4[2 * t]     = make_float4(s0, s1, s2, s3);
        ssp4[2 * t + 1] = make_float4(s4, s5, s6, s7);
        // no barrier: first read occurs after >=5 stage barriers
    }

    // ---- forward C2C 2048 (continuing from bufA) ----
    stage_r8<8,  false>(bufA, bufB, t, tld);          // A -> B
    stage_r8<64, false>(bufB, bufA, t, tld);          // B -> A
    stage_r4_512<false, true>(bufA, bufB, t, tld);    // A -> B (Z in B)

    // ---- FUSED: unpack rfft -> power spectrum -> irfft pack, B -> A ----
    {
#pragma unroll
        for (int i = 0; i < 4; i++) {
            int k = t + 256 * i;                      // k in [0,1024)
            float2 Za = bufB[IDX(k)];
            float2 Zb = bufB[IDX((2048 - k) & 2047)];
            float hex = 0.5f * (Za.x + Zb.x), hey = 0.5f * (Za.y - Zb.y);
            float hox = 0.5f * (Za.y + Zb.y), hoy = -0.5f * (Za.x - Zb.x);
            float s, c;
            sincospif((float)k * (1.0f / 2048.0f), &s, &c);
            float ux = c * hox + s * hoy;
            float uy = c * hoy - s * hox;
            float ax = hex + ux, ay = hey + uy;
            float bx = hex - ux, by = hey - uy;
            float Sk = ax * ax + ay * ay;
            float Sm = bx * bx + by * by;
            float A  = Sk + Sm, dS = Sk - Sm;
            bufA[IDX(k)] = make_float2(0.5f * (A - s * dS), 0.5f * (c * dS));
            if (k > 0)
                bufA[IDX(2048 - k)] = make_float2(0.5f * (A + s * dS), 0.5f * (c * dS));
        }
        if (t == 0) {
            float2 Zn = bufB[IDX(1024)];
            bufA[IDX(1024)] = make_float2(Zn.x * Zn.x + Zn.y * Zn.y, 0.f);
        }
    }
    __syncthreads();

    // ---- inverse C2C 2048 (outputs [0,1024) only) ----
    stage_r8<1,  true>(bufA, bufB, t, tld);           // A -> B (no twiddle)
    stage_r8<8,  true>(bufB, bufA, t, tld);           // B -> A
    stage_r8<64, true>(bufA, bufB, t, tld);           // A -> B
    stage_r4_512<true, false>(bufB, bufA, t, tld);    // B -> A (half store)

    // ---- d_raw[k] = ss[W-k] + (ss[W]-ss[k]) - 2 r[k], all vector loads ----
    const int k0 = 8 * t;
    float dr[8];
    {
        float sW = ((const float*)ssp4)[2047];
        float4 f0 = ssq4[2 * t], f1 = ssq4[2 * t + 1];                 // ss[8t+j]
        float4 b0 = ssp4[2 * (255 - t)], b1 = ssp4[2 * (255 - t) + 1]; // ssp[2040-8t..2047-8t]
        float fwd[8]  = {f0.x, f0.y, f0.z, f0.w, f1.x, f1.y, f1.z, f1.w};
        float bck[8]  = {b1.w, b1.z, b1.y, b1.x, b0.w, b0.z, b0.y, b0.x}; // ss[2048-(8t+j)]
        const float inv = 1.0f / 2048.0f;
        const int rb = (4 * t) ^ ((t >> 2) & 15);     // IDX(4t+q) == rb ^ q
#pragma unroll
        for (int q = 0; q < 4; q++) {
            float2 wv = bufA[rb ^ q];
            float r0 = wv.x * inv, r1 = wv.y * inv;
            dr[2 * q]     = bck[2 * q]     + (sW - fwd[2 * q])     - 2.f * r0;
            dr[2 * q + 1] = bck[2 * q + 1] + (sW - fwd[2 * q + 1]) - 2.f * r1;
        }
    }
    if (t == 0) dr[0] = 0.f;
    // no barrier: bufB reads finished at last stage's barrier; warpAgg quiet since scan1

    // ---- scan 2: cumsum over lags, normalize -> d0s (reuse bufB), vector stores ----
    float* d0s = (float*)bufB;
    {
        float run = 0.f;
#pragma unroll
        for (int j = 0; j < 8; j++) { run += dr[j]; pr[j] = run; }
        float ts = run, sc = run;
#pragma unroll
        for (int off = 1; off < 32; off <<= 1) {
            float o = __shfl_up_sync(0xffffffffu, sc, off);
            if (lane >= off) sc += o;
        }
        if (lane == 31) warpAgg[wid] = sc;
        __syncthreads();
        float wOff = 0.f;
#pragma unroll
        for (int w = 0; w < 8; w++) if (w < wid) wOff += warpAgg[w];
        float tOff = wOff + sc - ts;
        float vv[8];
#pragma unroll
        for (int j = 0; j < 8; j++) {
            int k = k0 + j;
            float cum = tOff + pr[j];
            vv[j] = (float)k * dr[j] / (cum + 1e-7f);
        }
        if (t == 0) vv[0] = 1.0f;
        ((float4*)d0s)[2 * t]     = make_float4(vv[0], vv[1], vv[2], vv[3]);
        ((float4*)d0s)[2 * t + 1] = make_float4(vv[4], vv[5], vv[6], vv[7]);
    }
    __syncthreads();

    // ---- epilogue: fractional-lag linear interpolation gather (no swizzle) ----
    float* yo = y + (size_t)blockIdx.x * M;
    for (int m = t; m < M; m += 256) {
        float4 p = g_lagpack[m];
        float lag = p.x;
        int fi = __float_as_int(p.y), ci = __float_as_int(p.z);
        float dfl = d0s[fi], dce = d0s[ci];
        float numer = (lag - (float)fi) * (dce - dfl);
        float denom = (float)(ci - fi);
        yo[m] = numer / denom + dfl;
    }
}

extern "C" void kernel_launch(void* const* d_in, const int* in_sizes, int n_in,
                              void* d_out, int out_size) {
    const float* x = (const float*)d_in[0];
    int total = in_sizes[0];
    int B = total / FRAME;
    int M = out_size / B;
    setup_kernel<<<(M + 255) / 256, 256>>>(M);
    yin_fft_kernel<<<B, 256>>>(x, (float*)d_out, M);
}

// round 12
// speedup vs baseline: 1.0421x; 1.0421x over previous
#include <cuda_runtime.h>
#include <cmath>
#include <cstring>

#define FRAME 2048
#define IDX(i) ((i) ^ (((i) >> 4) & 15))   // float2 FFT-buffer swizzle
#define SSW(i) ((i) ^ (((i) >> 5) & 31))   // float scan-array swizzle

// ---- device-global lag table, filled from host via async memcpy-to-symbol ----
__device__ float4 g_lagpack[2048];    // (lag, floor_bits, ceil_bits, 0)

__device__ __forceinline__ float2 cmul(float2 a, float2 b) {
    return make_float2(fmaf(a.x, b.x, -a.y * b.y), fmaf(a.x, b.y, a.y * b.x));
}
__device__ __forceinline__ float2 cadd(float2 a, float2 b) { return make_float2(a.x + b.x, a.y + b.y); }
__device__ __forceinline__ float2 csub(float2 a, float2 b) { return make_float2(a.x - b.x, a.y - b.y); }

template<bool INV>
__device__ __forceinline__ void dft4(float2 a, float2 b, float2 c, float2 d, float2* o) {
    float2 p = cadd(a, c), m = csub(a, c);
    float2 q = cadd(b, d), n = csub(b, d);
    o[0] = cadd(p, q);
    o[2] = csub(p, q);
    if (!INV) { o[1] = make_float2(m.x + n.y, m.y - n.x); o[3] = make_float2(m.x - n.y, m.y + n.x); }
    else      { o[1] = make_float2(m.x - n.y, m.y + n.x); o[3] = make_float2(m.x + n.y, m.y - n.x); }
}

template<bool INV>
__device__ __forceinline__ void omega8(const float2* O, float2& o1, float2& o2, float2& o3) {
    const float s2 = 0.70710678118654752f;
    if (!INV) {
        o1 = make_float2(s2 * (O[1].x + O[1].y), s2 * (O[1].y - O[1].x));
        o2 = make_float2(O[2].y, -O[2].x);
        o3 = make_float2(s2 * (O[3].y - O[3].x), -s2 * (O[3].x + O[3].y));
    } else {
        o1 = make_float2(s2 * (O[1].x - O[1].y), s2 * (O[1].y + O[1].x));
        o2 = make_float2(-O[2].y, O[2].x);
        o3 = make_float2(-s2 * (O[3].x + O[3].y), s2 * (O[3].x - O[3].y));
    }
}

// compile-time store-offset constant: IDX(base + m*NS) == b2 ^ soff<NS>(m)
template<int NS>
__device__ __forceinline__ constexpr int soff(int m) {
    return NS == 1 ? m
         : NS == 8 ? ((m << 3) | ((m >> 1) & 3))
                   : ((m << 6) | ((m & 3) << 2));   // NS == 64
}
// per-thread store base (swizzle pre-applied), per NS
template<int NS>
__device__ __forceinline__ int sbase(int t) {
    if (NS == 1)  return (8 * t) ^ ((t >> 1) & 15);
    if (NS == 8)  return (((t >> 3) << 6) | (t & 7)) ^ (((t >> 3) & 3) << 2);
    /* NS == 64 */ return (((t >> 6) << 9) | (t & 63)) ^ ((t >> 4) & 3);
}

// ---- generic radix-8 Stockham stage (smem -> smem), computed twiddles ----
template<int NS, bool INV>
__device__ __forceinline__ void stage_r8(const float2* in, float2* out, int t, int tld) {
    float2 v[8];
#pragma unroll
    for (int k = 0; k < 8; k++) v[k] = in[tld + 256 * k];
    const int jm = t & (NS - 1);
    if (NS > 1) {
        float s, c;
        sincospif((float)jm * (1.0f / (4.0f * NS)), &s, &c);
        if (!INV) s = -s;
        float2 w1 = make_float2(c, s);
        v[1] = cmul(v[1], w1);
        float2 w2 = cmul(w1, w1);
        v[2] = cmul(v[2], w2);
        float2 w3 = cmul(w2, w1);
        v[3] = cmul(v[3], w3);
        float2 w4 = cmul(w2, w2);
        v[4] = cmul(v[4], w4);
        v[5] = cmul(v[5], cmul(w4, w1));
        v[6] = cmul(v[6], cmul(w4, w2));
        v[7] = cmul(v[7], cmul(w4, w3));
    }
    float2 E[4], O[4];
    dft4<INV>(v[0], v[2], v[4], v[6], E);
    dft4<INV>(v[1], v[3], v[5], v[7], O);
    float2 o1, o2, o3;
    omega8<INV>(O, o1, o2, o3);
    const int b2 = sbase<NS>(t);
    out[b2 ^ soff<NS>(0)] = cadd(E[0], O[0]);
    out[b2 ^ soff<NS>(4)] = csub(E[0], O[0]);
    out[b2 ^ soff<NS>(1)] = cadd(E[1], o1);
    out[b2 ^ soff<NS>(5)] = csub(E[1], o1);
    out[b2 ^ soff<NS>(2)] = cadd(E[2], o2);
    out[b2 ^ soff<NS>(6)] = csub(E[2], o2);
    out[b2 ^ soff<NS>(3)] = cadd(E[3], o3);
    out[b2 ^ soff<NS>(7)] = csub(E[3], o3);
    __syncthreads();
}

// ---- forward stage 1 (NS=1): reads 4 nonzero inputs from GLOBAL, v[4..7]=0 ----
// NOTE: does NOT end with a barrier — caller supplies the shared one.
__device__ __forceinline__ void stage1_fwd_zero(const float2* gx, float2* out, int t) {
    float2 v0 = gx[t], v1 = gx[t + 256], v2 = gx[t + 512], v3 = gx[t + 768];
    float2 E[4], O[4];
    E[0] = cadd(v0, v2);
    E[2] = csub(v0, v2);
    E[1] = make_float2(v0.x + v2.y, v0.y - v2.x);
    E[3] = make_float2(v0.x - v2.y, v0.y + v2.x);
    O[0] = cadd(v1, v3);
    O[2] = csub(v1, v3);
    O[1] = make_float2(v1.x + v3.y, v1.y - v3.x);
    O[3] = make_float2(v1.x - v3.y, v1.y + v3.x);
    float2 o1, o2, o3;
    omega8<false>(O, o1, o2, o3);
    const int b2 = sbase<1>(t);
    out[b2 ^ 0] = cadd(E[0], O[0]);
    out[b2 ^ 4] = csub(E[0], O[0]);
    out[b2 ^ 1] = cadd(E[1], o1);
    out[b2 ^ 5] = csub(E[1], o1);
    out[b2 ^ 2] = cadd(E[2], o2);
    out[b2 ^ 6] = csub(E[2], o2);
    out[b2 ^ 3] = cadd(E[3], o3);
    out[b2 ^ 7] = csub(E[3], o3);
}

// ---- final radix-4 stage (NS=512); STORE_ALL=false drops outputs >= 1024 ----
template<bool INV, bool STORE_ALL>
__device__ __forceinline__ void stage_r4_512(const float2* in, float2* out, int t, int tld) {
#pragma unroll
    for (int u = 0; u < 2; u++) {
        int j  = t + 256 * u;
        int jb = tld + 256 * u;
        float2 v0 = in[jb];
        float2 v1 = in[jb + 512];
        float2 v2 = in[jb + 1024];
        float2 v3 = in[jb + 1536];
        float s, c;
        sincospif((float)j * (1.0f / 1024.0f), &s, &c);
        if (!INV) s = -s;
        float2 w1 = make_float2(c, s);
        float2 w2 = cmul(w1, w1);
        float2 w3 = cmul(w2, w1);
        v1 = cmul(v1, w1); v2 = cmul(v2, w2); v3 = cmul(v3, w3);
        float2 a0 = cadd(v0, v2), a1 = csub(v0, v2);
        float2 a2 = cadd(v1, v3), a3 = csub(v1, v3);
        out[jb] = cadd(a0, a2);
        float2 y1 = (!INV) ? make_float2(a1.x + a3.y, a1.y - a3.x)
                           : make_float2(a1.x - a3.y, a1.y + a3.x);
        out[jb + 512] = y1;
        if (STORE_ALL) {
            out[jb + 1024] = csub(a0, a2);
            float2 y3 = (!INV) ? make_float2(a1.x - a3.y, a1.y + a3.x)
                               : make_float2(a1.x + a3.y, a1.y - a3.x);
            out[jb + 1536] = y3;
        }
    }
    __syncthreads();
}

// One CTA = one frame, 256 threads.
__global__ __launch_bounds__(256, 4) void yin_fft_kernel(
    const float* __restrict__ x, float* __restrict__ y, int M)
{
    __shared__ float2 bufA[2048];
    __shared__ float2 bufB[2048];
    __shared__ float  ss[2049];
    __shared__ float  warpAgg[8];

    const int t    = threadIdx.x;
    const int lane = t & 31;
    const int wid  = t >> 5;
    const int tld  = t ^ ((t >> 4) & 15);   // == IDX(t)
    const float* xf = x + (size_t)blockIdx.x * FRAME;

    // ---- FUSED: scan1 phase A + stage1 (G -> bufA), sharing ONE barrier ----
    float pr[8];
    float scanv;
    {
        float4 va = ((const float4*)xf)[2 * t];
        float4 vb = ((const float4*)xf)[2 * t + 1];
        float xr[8] = {va.x, va.y, va.z, va.w, vb.x, vb.y, vb.z, vb.w};
        float run = 0.f;
#pragma unroll
        for (int j = 0; j < 8; j++) { run += xr[j] * xr[j]; pr[j] = run; }
        float sc = run;
#pragma unroll
        for (int off = 1; off < 32; off <<= 1) {
            float o = __shfl_up_sync(0xffffffffu, sc, off);
            if (lane >= off) sc += o;
        }
        if (lane == 31) warpAgg[wid] = sc;
        scanv = sc - run;              // exclusive within-warp offset
    }
    stage1_fwd_zero((const float2*)xf, bufA, t);   // no internal barrier
    __syncthreads();                               // covers warpAgg AND bufA

    // ---- scan1 phase B: finish prefix sum of squares -> ss[0..2048] ----
    {
        float wOff = 0.f;
#pragma unroll
        for (int w = 0; w < 8; w++) if (w < wid) wOff += warpAgg[w];
        float tOff = wOff + scanv;
#pragma unroll
        for (int j = 0; j < 8; j++) ss[SSW(8 * t + j + 1)] = tOff + pr[j];
        if (t == 0) ss[SSW(0)] = 0.f;
        // no barrier: ss first read occurs after >=5 stage barriers
    }

    // ---- forward C2C 2048 (continuing from bufA) ----
    stage_r8<8,  false>(bufA, bufB, t, tld);          // A -> B
    stage_r8<64, false>(bufB, bufA, t, tld);          // B -> A
    stage_r4_512<false, true>(bufA, bufB, t, tld);    // A -> B (Z in B)

    // ---- FUSED: unpack rfft -> power spectrum -> irfft pack, B -> A ----
    {
#pragma unroll
        for (int i = 0; i < 4; i++) {
            int k = t + 256 * i;                      // k in [0,1024)
            float2 Za = bufB[IDX(k)];
            float2 Zb = bufB[IDX((2048 - k) & 2047)];
            float hex = 0.5f * (Za.x + Zb.x), hey = 0.5f * (Za.y - Zb.y);
            float hox = 0.5f * (Za.y + Zb.y), hoy = -0.5f * (Za.x - Zb.x);
            float s, c;
            sincospif((float)k * (1.0f / 2048.0f), &s, &c);
            float ux = c * hox + s * hoy;
            float uy = c * hoy - s * hox;
            float ax = hex + ux, ay = hey + uy;
            float bx = hex - ux, by = hey - uy;
            float Sk = ax * ax + ay * ay;
            float Sm = bx * bx + by * by;
            float A  = Sk + Sm, dS = Sk - Sm;
            bufA[IDX(k)] = make_float2(0.5f * (A - s * dS), 0.5f * (c * dS));
            if (k > 0)
                bufA[IDX(2048 - k)] = make_float2(0.5f * (A + s * dS), 0.5f * (c * dS));
        }
        if (t == 0) {
            float2 Zn = bufB[IDX(1024)];
            bufA[IDX(1024)] = make_float2(Zn.x * Zn.x + Zn.y * Zn.y, 0.f);
        }
    }
    __syncthreads();

    // ---- inverse C2C 2048 (outputs [0,1024) only) ----
    stage_r8<1,  true>(bufA, bufB, t, tld);           // A -> B (no twiddle)
    stage_r8<8,  true>(bufB, bufA, t, tld);           // B -> A
    stage_r8<64, true>(bufA, bufB, t, tld);           // A -> B
    stage_r4_512<true, false>(bufB, bufA, t, tld);    // B -> A (half store)

    // ---- d_raw[k] = ss[W-k] + (ss[W]-ss[k]) - 2 r[k] ----
    const int k0 = 8 * t;
    float dr[8];
    {
        float sW = ss[SSW(2048)];
        const float inv = 1.0f / 2048.0f;
        const int rb = (4 * t) ^ ((t >> 2) & 15);     // IDX(4t+q) == rb ^ q (q in bits 0-1)
#pragma unroll
        for (int q = 0; q < 4; q++) {
            float2 wv = bufA[rb ^ q];
            float r0 = wv.x * inv, r1 = wv.y * inv;
            int k = k0 + 2 * q;
            dr[2 * q]     = ss[SSW(FRAME - k)]     + (sW - ss[SSW(k)])     - 2.f * r0;
            dr[2 * q + 1] = ss[SSW(FRAME - k - 1)] + (sW - ss[SSW(k + 1)]) - 2.f * r1;
        }
    }
    if (t == 0) dr[0] = 0.f;
    // no barrier: bufB reads finished at last stage's barrier; warpAgg quiet since scan1

    // ---- scan 2: cumsum over lags, normalize -> d0s (reuse bufB, swizzled) ----
    float* d0s = (float*)bufB;
    {
        float run = 0.f;
#pragma unroll
        for (int j = 0; j < 8; j++) { run += dr[j]; pr[j] = run; }
        float ts = run, sc = run;
#pragma unroll
        for (int off = 1; off < 32; off <<= 1) {
            float o = __shfl_up_sync(0xffffffffu, sc, off);
            if (lane >= off) sc += o;
        }
        if (lane == 31) warpAgg[wid] = sc;
        __syncthreads();
        float wOff = 0.f;
#pragma unroll
        for (int w = 0; w < 8; w++) if (w < wid) wOff += warpAgg[w];
        float tOff = wOff + sc - ts;
#pragma unroll
        for (int j = 0; j < 8; j++) {
            int k = k0 + j;
            float cum = tOff + pr[j];
            float val = (float)k * dr[j] / (cum + 1e-7f);
            d0s[SSW(k)] = (k == 0) ? 1.0f : val;
        }
    }
    __syncthreads();

    // ---- epilogue: fractional-lag linear interpolation gather ----
    float* yo = y + (size_t)blockIdx.x * M;
    for (int m = t; m < M; m += 256) {
        float4 p = g_lagpack[m];
        float lag = p.x;
        int fi = __float_as_int(p.y), ci = __float_as_int(p.z);
        float dfl = d0s[SSW(fi)], dce = d0s[SSW(ci)];
        float numer = (lag - (float)fi) * (dce - dfl);
        float denom = (float)(ci - fi);
        yo[m] = numer / denom + dfl;
    }
}

// ---- host-side lag table (input-independent; deterministic) ----
static float4 h_lagpack[2048];

static inline float bits_to_float(int i) { float f; std::memcpy(&f, &i, 4); return f; }

extern "C" void kernel_launch(void* const* d_in, const int* in_sizes, int n_in,
                              void* d_out, int out_size) {
    const float* x = (const float*)d_in[0];
    int total = in_sizes[0];
    int B = total / FRAME;
    int M = out_size / B;
    int Mc = M < 2048 ? M : 2048;

    for (int m = 0; m < Mc; m++) {
        double midi64 = 5.0 + (double)m * 0.05;
        float  midi32 = (float)midi64;
        double e      = ((double)midi32 - 69.0) / 12.0;
        double lag64  = 22050.0 / (440.0 * exp2(e));
        float  lag32  = (float)lag64;
        int fi = (int)floorf(lag32), ci = (int)ceilf(lag32);
        h_lagpack[m] = make_float4(lag32, bits_to_float(fi), bits_to_float(ci), 0.f);
    }
    cudaMemcpyToSymbolAsync(g_lagpack, h_lagpack, sizeof(float4) * (size_t)Mc, 0,
                            cudaMemcpyHostToDevice, 0);
    yin_fft_kernel<<<B, 256>>>(x, (float*)d_out, M);
}